// round 14
// baseline (speedup 1.0000x reference)
#include <cuda_runtime.h>
#include <cstdint>

// VarConvND via tcgen05 TF32 per-location GEMM (sm_103a), SIMT fallback body
// for the plain compute_103 PTX pass (never selected at runtime on GB300).
//
//   out[b, co, s] = sum_k (unfold(X)[b, k, s] + bias[s]) * weight[s, k, co]
// Decomposed: out = unfold(X)^T W + bias[s] * colsum_k(W[s,:,co]).
//
// ROLE SWAP: A-operand = W[co][k] (M=co pad 128), B-operand = act[b][k] (N=64).
// K permuted tap-major (k' = tap*128 + c): activation chunk = contiguous 8KB
// block of Xt(y,x,b,c), filled with 2xLDG.128/thread. W chunk: transposing
// 8xLDG.32 (coalesced, nL=1).
//
// Round 12: 3-stage A/B ring (dynamic smem ~50KB, occupancy 4 preserved) to
// cover W-DRAM latency with ~2 chunks of slack instead of ~1.
//
// Pass 1: X (B,C,H,W) -> Xt (H,W,B,C), tf32-rounded (rna).
// Pass 2: one block per s. D[co][b] -> scratch[s][co][b] (coalesced).
// Pass 3: scratch (s, co, b) -> out (b*64+co, s).

#if defined(__CUDA_ARCH_FEAT_SM103_ALL) || defined(__CUDA_ARCH_FEAT_SM100_ALL)
#define HAS_TCGEN05 1
#else
#define HAS_TCGEN05 0
#endif

__device__ float g_Xt[32 * 32 * 64 * 128];      // (y, x, b, c) 33.5 MB
__device__ float g_scratch[1024 * 64 * 64];     // (s, co, b)   16.8 MB

// smem layout (byte offsets from 1024-aligned base):
//   A(W) stages  [0, 24576)       3 x 8KB
//   B(act) stages[24576, 49152)   3 x 8KB
//   mbar         [49152, 49176)   3 x u64
//   tmem ptr     [49176, 49180)
//   cs4          [49184, 50208)   4 x 64 float
//   cs           [50208, 50464)   64 float
#define SM_B    24576
#define SM_MBAR 49152
#define SM_TPTR 49176
#define SM_CS4  49184
#define SM_CS   50208
#define DYN_BYTES (50464 + 1024)

// ---------------------------------------------------------------------------
// helpers
// ---------------------------------------------------------------------------
__device__ __forceinline__ uint32_t smem_u32(const void* p) {
    uint32_t a;
    asm("{ .reg .u64 t; cvta.to.shared.u64 t, %1; cvt.u32.u64 %0, t; }" : "=r"(a) : "l"(p));
    return a;
}
__device__ __forceinline__ uint32_t f2tf32(float f) {
    uint32_t r;
    asm("cvt.rna.tf32.f32 %0, %1;" : "=r"(r) : "f"(f));
    return r;
}
#define SWZ(o) ((o) ^ (((o) >> 3) & 0x70))

#if HAS_TCGEN05
__device__ __forceinline__ uint32_t elect_one() {
    uint32_t p;
    asm volatile("{ .reg .pred p; elect.sync _|p, 0xFFFFFFFF; selp.b32 %0,1,0,p; }" : "=r"(p));
    return p;
}

// K-major SW128: LBO=1, SBO=64 (proven rounds 4-11)
static constexpr uint64_t DESC_BASE =
    (uint64_t(2) << 61) | (uint64_t(1) << 46) | (uint64_t(64) << 32) | (uint64_t(1) << 16);
__device__ __forceinline__ uint64_t make_desc(uint32_t addr) {
    return DESC_BASE | ((uint64_t)(addr >> 4) & 0x3FFF);
}

// idesc kind::tf32: dtype=F32(1)<<4, atype=TF32(2)<<7, btype=TF32(2)<<10,
// N=64 -> 8<<17, M=128 -> 8<<24   (proven rounds 4-11)
#define IDESC_TF32 0x8100910u

__device__ __forceinline__ void mma_tf32(uint32_t d, uint64_t ad, uint64_t bd, uint32_t en) {
    asm volatile(
        "{\n\t.reg .pred p;\n\tsetp.ne.u32 p, %4, 0;\n\t"
        "tcgen05.mma.cta_group::1.kind::tf32 [%0], %1, %2, %3, {%5,%5,%5,%5}, p;\n\t}"
        :: "r"(d), "l"(ad), "l"(bd), "r"(IDESC_TF32), "r"(en), "r"(0u) : "memory");
}

#define MBARRIER_INIT(a, c) \
    asm volatile("mbarrier.init.shared.b64 [%0], %1;" :: "r"(a), "r"(c) : "memory")

#define MBAR_WAIT(addr, ph) do { \
    uint32_t _a = (addr), _p = (ph) & 1, _d; \
    asm volatile("{\n\t.reg .pred p;\n\tmbarrier.try_wait.parity.acquire.cta.shared::cta.b64 p, [%1], %2;\n\tselp.b32 %0,1,0,p;\n\t}" \
        : "=r"(_d) : "r"(_a), "r"(_p) : "memory"); \
    while (!_d) { \
        asm volatile("{\n\t.reg .pred p;\n\tmbarrier.try_wait.parity.acquire.cta.shared::cta.b64 p, [%1], %2, 0x989680;\n\tselp.b32 %0,1,0,p;\n\t}" \
            : "=r"(_d) : "r"(_a), "r"(_p) : "memory"); \
    } \
} while (0)

#define TCG_COMMIT(mb) \
    asm volatile("tcgen05.commit.cta_group::1.mbarrier::arrive::one.shared::cluster.b64 [%0];" :: "r"(mb) : "memory")
#define TCG_ALLOC(sa, n) \
    asm volatile("tcgen05.alloc.cta_group::1.sync.aligned.shared::cta.b32 [%0], %1;" :: "r"(sa), "r"(n) : "memory")
#define TCG_DEALLOC(t, n) \
    asm volatile("tcgen05.dealloc.cta_group::1.sync.aligned.b32 %0, %1;" :: "r"(t), "r"(n))
#define TCG_RELINQ() \
    asm volatile("tcgen05.relinquish_alloc_permit.cta_group::1.sync.aligned;")
#define TCG_WAIT_LD() asm volatile("tcgen05.wait::ld.sync.aligned;" ::: "memory")
#define TCG_FENCE_AFTER() asm volatile("tcgen05.fence::after_thread_sync;" ::: "memory")

#define TCG_LD_X32(r, ta) \
    asm volatile("tcgen05.ld.sync.aligned.32x32b.x32.b32 " \
        "{%0,%1,%2,%3,%4,%5,%6,%7,%8,%9,%10,%11,%12,%13,%14,%15," \
        "%16,%17,%18,%19,%20,%21,%22,%23,%24,%25,%26,%27,%28,%29,%30,%31}, [%32];" \
        : "=r"((r)[0]), "=r"((r)[1]), "=r"((r)[2]), "=r"((r)[3]), \
          "=r"((r)[4]), "=r"((r)[5]), "=r"((r)[6]), "=r"((r)[7]), \
          "=r"((r)[8]), "=r"((r)[9]), "=r"((r)[10]), "=r"((r)[11]), \
          "=r"((r)[12]), "=r"((r)[13]), "=r"((r)[14]), "=r"((r)[15]), \
          "=r"((r)[16]), "=r"((r)[17]), "=r"((r)[18]), "=r"((r)[19]), \
          "=r"((r)[20]), "=r"((r)[21]), "=r"((r)[22]), "=r"((r)[23]), \
          "=r"((r)[24]), "=r"((r)[25]), "=r"((r)[26]), "=r"((r)[27]), \
          "=r"((r)[28]), "=r"((r)[29]), "=r"((r)[30]), "=r"((r)[31]) \
        : "r"(ta))
#endif  // HAS_TCGEN05

// ---------------------------------------------------------------------------
// Pass 1: X (B=64, C=128, H=32, W=32) -> Xt (H, W, B, C), tf32-rounded.
// ---------------------------------------------------------------------------
__global__ void __launch_bounds__(256) transpose_kernel(const float* __restrict__ X) {
    __shared__ float sm[128][33];
    const int bx = blockIdx.x;
    const int b  = bx >> 5;    // 0..63
    const int yy = bx & 31;    // 0..31
    const int t  = threadIdx.x;

    #pragma unroll
    for (int p = 0; p < 16; p++) {
        const int c = p * 8 + (t >> 5);
        const int x = t & 31;
        sm[c][x] = X[(((b * 128 + c) * 32 + yy) << 5) + x];
    }
    __syncthreads();
    #pragma unroll
    for (int q = 0; q < 16; q++) {
        const int x = q * 2 + (t >> 7);
        const int c = t & 127;
        g_Xt[((((yy << 5) + x) << 6) + b) * 128 + c] = __uint_as_float(f2tf32(sm[c][x]));
    }
}

// ---------------------------------------------------------------------------
// Pass 2: per-location GEMM (role-swapped, tap-major K, 3-stage pipeline)
// ---------------------------------------------------------------------------
__global__ void __launch_bounds__(256) varconv_kernel(
    const float* __restrict__ W, const float* __restrict__ bias)
{
    extern __shared__ __align__(16) char dyn[];
    const uint32_t rawb = smem_u32(dyn);
    const uint32_t smb  = (rawb + 1023u) & ~1023u;
    char* smc = dyn + (smb - rawb);

    const int s = blockIdx.x;
    const int y = s >> 5, x0 = s & 31;
    const int tid = threadIdx.x;
    const float bs = bias[s];

#if HAS_TCGEN05
    const int wid = tid >> 5, lid = tid & 31;
    const int bq = tid & 63;        // co row (W / A-operand)
    const int kg = tid >> 6;        // k-subgroup 0..3 (8 k each)

    if (wid == 0) { TCG_ALLOC(smb + SM_TPTR, 64); TCG_RELINQ(); }
    if (tid == 0) {
        MBARRIER_INIT(smb + SM_MBAR,      1);
        MBARRIER_INIT(smb + SM_MBAR + 8,  1);
        MBARRIER_INIT(smb + SM_MBAR + 16, 1);
    }
    __syncthreads();
    uint32_t tmem;
    asm("ld.shared.b32 %0, [%1];" : "=r"(tmem) : "r"(smb + SM_TPTR));

    const float* Wp = W + (size_t)s * 73728 + bq;   // + co
    float csum = 0.0f;
    uint32_t wv[8];
    uint4 act0, act1;

    // Act fill: 8 lanes per b-row (16B granules): row = tid>>3, gj = tid&7.
    const int r0 = tid >> 3, gj = tid & 7;

    // chunk ci = tap*4 + q covers original k = (q*32 + j)*9 + tap, j=0..31.
    auto loadAB = [&](int ci) {
        const int tap = ci >> 2;
        const int q   = ci & 3;
        const int yy  = y  + tap / 3 - 1;
        const int xx  = x0 + tap % 3 - 1;
        const int kb  = q * 32 + kg * 8;        // c-base for W rows
        const float* wq = Wp + (size_t)(kb * 9 + tap) * 64;
        #pragma unroll
        for (int u = 0; u < 8; u++) {
            wv[u] = f2tf32(__ldg(wq + u * 576));
            csum += __uint_as_float(wv[u]);
        }
        if (((unsigned)yy < 32u) && ((unsigned)xx < 32u)) {
            const float* base = g_Xt + (size_t)((((yy << 5) + xx) << 6)) * 128 + q * 32 + gj * 4;
            act0 = *(const uint4*)(base + (size_t)r0 * 128);
            act1 = *(const uint4*)(base + (size_t)(r0 + 32) * 128);
        } else {
            act0 = make_uint4(0, 0, 0, 0);
            act1 = make_uint4(0, 0, 0, 0);
        }
    };

    loadAB(0);
    int ph0 = 0, ph1 = 0, ph2 = 0;
    const uint32_t woff = (uint32_t)bq * 128 + (uint32_t)kg * 32;
    const uint32_t wsw0 = SWZ(woff), wsw1 = SWZ(woff + 16);
    const uint32_t asw0 = SWZ((uint32_t)r0 * 128 + (uint32_t)gj * 16);
    const uint32_t asw1 = SWZ((uint32_t)(r0 + 32) * 128 + (uint32_t)gj * 16);

#define CHUNK(I, ST, PH) { \
    if ((I) >= 3) { MBAR_WAIT(smb + SM_MBAR + (ST) * 8, PH); PH ^= 1; } \
    *(uint4*)(smc + (ST) * 8192 + wsw0)        = make_uint4(wv[0], wv[1], wv[2], wv[3]); \
    *(uint4*)(smc + (ST) * 8192 + wsw1)        = make_uint4(wv[4], wv[5], wv[6], wv[7]); \
    *(uint4*)(smc + SM_B + (ST) * 8192 + asw0) = act0; \
    *(uint4*)(smc + SM_B + (ST) * 8192 + asw1) = act1; \
    if ((I) + 1 < 36) loadAB((I) + 1); \
    asm volatile("fence.proxy.async.shared::cta;" ::: "memory"); \
    __syncthreads(); \
    if (wid == 0 && elect_one()) { \
        uint64_t ad = make_desc(smb + (ST) * 8192); \
        uint64_t bd = make_desc(smb + SM_B + (ST) * 8192); \
        mma_tf32(tmem, ad,     bd,     (I) > 0 ? 1u : 0u); \
        mma_tf32(tmem, ad + 2, bd + 2, 1u); \
        mma_tf32(tmem, ad + 4, bd + 4, 1u); \
        mma_tf32(tmem, ad + 6, bd + 6, 1u); \
        TCG_COMMIT(smb + SM_MBAR + (ST) * 8); \
    } }

    for (int i = 0; i < 36; i += 3) {
        CHUNK(i,     0, ph0);
        CHUNK(i + 1, 1, ph1);
        CHUNK(i + 2, 2, ph2);
    }
#undef CHUNK

    // colsum reduction: cs[co] = sum over 4 kg partials
    ((float*)(smc + SM_CS4))[kg * 64 + bq] = csum;
    __syncthreads();
    if (tid < 64) {
        const float* c4 = (const float*)(smc + SM_CS4);
        ((float*)(smc + SM_CS))[tid] = c4[tid] + c4[64 + tid] + c4[128 + tid] + c4[192 + tid];
    }
    __syncthreads();

    MBAR_WAIT(smb + SM_MBAR,      ph0);
    MBAR_WAIT(smb + SM_MBAR + 8,  ph1);
    MBAR_WAIT(smb + SM_MBAR + 16, ph2);
    TCG_FENCE_AFTER();

    // D[co][b]: warps 0,1 read rows co=0..63, add bias*colsum[co], write
    // scratch[s][co][b] coalesced.
    if (wid < 2) {
        const int co = wid * 32 + lid;
        const float corr = bs * ((const float*)(smc + SM_CS))[co];
        float* dst = g_scratch + ((size_t)s * 64 + co) * 64;
        uint32_t dr[32];
        TCG_LD_X32(dr, tmem);
        TCG_WAIT_LD();
        #pragma unroll
        for (int c = 0; c < 32; c++)
            dr[c] = __float_as_uint(__uint_as_float(dr[c]) + corr);
        #pragma unroll
        for (int j = 0; j < 8; j++)
            ((uint4*)dst)[j] = make_uint4(dr[4 * j], dr[4 * j + 1], dr[4 * j + 2], dr[4 * j + 3]);
        TCG_LD_X32(dr, tmem + 32);
        TCG_WAIT_LD();
        #pragma unroll
        for (int c = 0; c < 32; c++)
            dr[c] = __float_as_uint(__uint_as_float(dr[c]) + corr);
        #pragma unroll
        for (int j = 0; j < 8; j++)
            ((uint4*)(dst + 32))[j] = make_uint4(dr[4 * j], dr[4 * j + 1], dr[4 * j + 2], dr[4 * j + 3]);
    }
    __syncthreads();
    if (wid == 0) TCG_DEALLOC(tmem, 64);

#else  // ------- SIMT fallback (plain compute_103 pass; not selected on GB300)
    float (*As)[68] = (float(*)[68])smc;
    float (*Bs)[64] = (float(*)[64])(smc + 32 * 68 * 4);
    const int tx = tid & 15;
    const int ty = tid >> 4;
    const float* Wp = W + (size_t)s * 73728;

    float acc[4][4];
    #pragma unroll
    for (int i = 0; i < 4; i++)
        #pragma unroll
        for (int j = 0; j < 4; j++) acc[i][j] = 0.0f;

    for (int k0 = 0; k0 < 1152; k0 += 32) {
        {
            const float4* src = (const float4*)(Wp + k0 * 64);
            float4* dstB = (float4*)(&Bs[0][0]);
            dstB[tid]       = src[tid];
            dstB[tid + 256] = src[tid + 256];
        }
        #pragma unroll
        for (int i = 0; i < 2; i++) {
            const int kk = i * 16 + (tid >> 4);
            const int k  = k0 + kk;
            const int c   = k / 9;
            const int tap = k - c * 9;
            const int r   = tap / 3;
            const int cc  = tap - r * 3;
            const int yy = y + r - 1;
            const int xx = x0 + cc - 1;
            const int b4 = (tid & 15) << 2;
            float4 v = make_float4(0.f, 0.f, 0.f, 0.f);
            if (((unsigned)yy < 32u) && ((unsigned)xx < 32u)) {
                v.x = g_Xt[((((yy << 5) + xx) << 6) + b4 + 0) * 128 + c];
                v.y = g_Xt[((((yy << 5) + xx) << 6) + b4 + 1) * 128 + c];
                v.z = g_Xt[((((yy << 5) + xx) << 6) + b4 + 2) * 128 + c];
                v.w = g_Xt[((((yy << 5) + xx) << 6) + b4 + 3) * 128 + c];
            }
            v.x += bs; v.y += bs; v.z += bs; v.w += bs;
            *(float4*)&As[kk][b4] = v;
        }
        __syncthreads();
        #pragma unroll
        for (int kk = 0; kk < 32; kk++) {
            const float4 a = *(const float4*)&As[kk][ty << 2];
            const float4 b = *(const float4*)&Bs[kk][tx << 2];
            acc[0][0] += a.x * b.x; acc[0][1] += a.x * b.y; acc[0][2] += a.x * b.z; acc[0][3] += a.x * b.w;
            acc[1][0] += a.y * b.x; acc[1][1] += a.y * b.y; acc[1][2] += a.y * b.z; acc[1][3] += a.y * b.w;
            acc[2][0] += a.z * b.x; acc[2][1] += a.z * b.y; acc[2][2] += a.z * b.z; acc[2][3] += a.z * b.w;
            acc[3][0] += a.w * b.x; acc[3][1] += a.w * b.y; acc[3][2] += a.w * b.z; acc[3][3] += a.w * b.w;
        }
        __syncthreads();
    }
    #pragma unroll
    for (int i = 0; i < 4; i++) {
        const int b = (ty << 2) + i;
        #pragma unroll
        for (int j = 0; j < 4; j++) {
            const int co = (tx << 2) + j;
            g_scratch[((size_t)s * 64 + co) * 64 + b] = acc[i][j];
        }
    }
#endif
}

// ---------------------------------------------------------------------------
// Pass 3: scratch (s, co, b) -> out (b*64+co, s)
// ---------------------------------------------------------------------------
__global__ void __launch_bounds__(256) out_transpose(float* __restrict__ out) {
    __shared__ float tile[64][65];   // [s][b]
    const int co = blockIdx.x;
    const int s0 = blockIdx.y * 64;
    const int t  = threadIdx.x;

    #pragma unroll
    for (int r = 0; r < 4; r++) {
        const int gi = r * 256 + t;
        const int si = gi >> 4;
        const int gjj = gi & 15;
        const float4 v = *(const float4*)(g_scratch + (size_t)(s0 + si) * 4096 + co * 64 + gjj * 4);
        tile[si][gjj * 4 + 0] = v.x;
        tile[si][gjj * 4 + 1] = v.y;
        tile[si][gjj * 4 + 2] = v.z;
        tile[si][gjj * 4 + 3] = v.w;
    }
    __syncthreads();
    #pragma unroll
    for (int r = 0; r < 4; r++) {
        const int gi = r * 256 + t;
        const int b  = gi >> 4;
        const int sj = gi & 15;
        float4 v;
        v.x = tile[sj * 4 + 0][b];
        v.y = tile[sj * 4 + 1][b];
        v.z = tile[sj * 4 + 2][b];
        v.w = tile[sj * 4 + 3][b];
        *(float4*)(out + (size_t)(b * 64 + co) * 1024 + s0 + sj * 4) = v;
    }
}

extern "C" void kernel_launch(void* const* d_in, const int* in_sizes, int n_in,
                              void* d_out, int out_size) {
    const float* X    = (const float*)d_in[0];
    const float* W    = (const float*)d_in[1];
    const float* bias = (const float*)d_in[2];
    float* out = (float*)d_out;

    cudaFuncSetAttribute(varconv_kernel,
                         cudaFuncAttributeMaxDynamicSharedMemorySize, DYN_BYTES);

    transpose_kernel<<<64 * 32, 256>>>(X);
    varconv_kernel<<<1024, 256, DYN_BYTES>>>(W, bias);
    out_transpose<<<dim3(64, 16), 256>>>(out);
}

// round 15
// speedup vs baseline: 1.6073x; 1.6073x over previous
#include <cuda_runtime.h>
#include <cuda_fp16.h>
#include <cstdint>

// VarConvND via tcgen05 FP16 per-location GEMM (sm_103a), SIMT fallback body
// for the plain compute_103 PTX pass (never selected at runtime on GB300).
//
//   out[b, co, s] = sum_k (unfold(X)[b, k, s] + bias[s]) * weight[s, k, co]
// Decomposed: out = unfold(X)^T W + bias[s] * colsum_k(W[s,:,co]).
//
// ROLE SWAP: A-operand = W[co][k] (M=co pad 128), B-operand = act[b][k] (N=64).
// K permuted tap-major; chunk = (tap, c-half): K64 per chunk, 18 chunks.
// Operands fp16 (same 10 mantissa bits as tf32), fp32 accumulate.
// Act tile rows are 128B contiguous fp16 -> LDG.128 nL=1.
//
// Pass 1: X (B,C,H,W) -> XtH (H,W,B,C) fp16 (rn).  16.8 MB (halved traffic).
// Pass 2: one block per s, 2-stage pipeline (round-11 proven skeleton).
//         D[co][b] -> scratch[s][co][b] (coalesced).
// Pass 3: scratch (s, co, b) -> out (b*64+co, s).

#if defined(__CUDA_ARCH_FEAT_SM103_ALL) || defined(__CUDA_ARCH_FEAT_SM100_ALL)
#define HAS_TCGEN05 1
#else
#define HAS_TCGEN05 0
#endif

__device__ __half g_XtH[32 * 32 * 64 * 128];    // (y, x, b, c) 16.8 MB
__device__ float g_scratch[1024 * 64 * 64];     // (s, co, b)   16.8 MB

// ---------------------------------------------------------------------------
// helpers
// ---------------------------------------------------------------------------
__device__ __forceinline__ uint32_t smem_u32(const void* p) {
    uint32_t a;
    asm("{ .reg .u64 t; cvta.to.shared.u64 t, %1; cvt.u32.u64 %0, t; }" : "=r"(a) : "l"(p));
    return a;
}
__device__ __forceinline__ uint32_t pack_f16x2(float lo, float hi) {
    uint32_t r;
    asm("cvt.rn.f16x2.f32 %0, %1, %2;" : "=r"(r) : "f"(hi), "f"(lo));
    return r;
}
#define SWZ(o) ((o) ^ (((o) >> 3) & 0x70))

#if HAS_TCGEN05
__device__ __forceinline__ uint32_t elect_one() {
    uint32_t p;
    asm volatile("{ .reg .pred p; elect.sync _|p, 0xFFFFFFFF; selp.b32 %0,1,0,p; }" : "=r"(p));
    return p;
}

// K-major SW128: LBO=1, SBO=64 (proven rounds 4-12; 128B rows)
static constexpr uint64_t DESC_BASE =
    (uint64_t(2) << 61) | (uint64_t(1) << 46) | (uint64_t(64) << 32) | (uint64_t(1) << 16);
__device__ __forceinline__ uint64_t make_desc(uint32_t addr) {
    return DESC_BASE | ((uint64_t)(addr >> 4) & 0x3FFF);
}

// idesc kind::f16 (fp16 x fp16 -> f32): dtype=F32(1)<<4, atype=FP16(0)<<7,
// btype=FP16(0)<<10, N=64 -> 8<<17, M=128 -> 8<<24
#define IDESC_F16 0x8100010u

__device__ __forceinline__ void mma_f16(uint32_t d, uint64_t ad, uint64_t bd, uint32_t en) {
    asm volatile(
        "{\n\t.reg .pred p;\n\tsetp.ne.u32 p, %4, 0;\n\t"
        "tcgen05.mma.cta_group::1.kind::f16 [%0], %1, %2, %3, {%5,%5,%5,%5}, p;\n\t}"
        :: "r"(d), "l"(ad), "l"(bd), "r"(IDESC_F16), "r"(en), "r"(0u) : "memory");
}

#define MBARRIER_INIT(a, c) \
    asm volatile("mbarrier.init.shared.b64 [%0], %1;" :: "r"(a), "r"(c) : "memory")

#define MBAR_WAIT(addr, ph) do { \
    uint32_t _a = (addr), _p = (ph) & 1, _d; \
    asm volatile("{\n\t.reg .pred p;\n\tmbarrier.try_wait.parity.acquire.cta.shared::cta.b64 p, [%1], %2;\n\tselp.b32 %0,1,0,p;\n\t}" \
        : "=r"(_d) : "r"(_a), "r"(_p) : "memory"); \
    while (!_d) { \
        asm volatile("{\n\t.reg .pred p;\n\tmbarrier.try_wait.parity.acquire.cta.shared::cta.b64 p, [%1], %2, 0x989680;\n\tselp.b32 %0,1,0,p;\n\t}" \
            : "=r"(_d) : "r"(_a), "r"(_p) : "memory"); \
    } \
} while (0)

#define TCG_COMMIT(mb) \
    asm volatile("tcgen05.commit.cta_group::1.mbarrier::arrive::one.shared::cluster.b64 [%0];" :: "r"(mb) : "memory")
#define TCG_ALLOC(sa, n) \
    asm volatile("tcgen05.alloc.cta_group::1.sync.aligned.shared::cta.b32 [%0], %1;" :: "r"(sa), "r"(n) : "memory")
#define TCG_DEALLOC(t, n) \
    asm volatile("tcgen05.dealloc.cta_group::1.sync.aligned.b32 %0, %1;" :: "r"(t), "r"(n))
#define TCG_RELINQ() \
    asm volatile("tcgen05.relinquish_alloc_permit.cta_group::1.sync.aligned;")
#define TCG_WAIT_LD() asm volatile("tcgen05.wait::ld.sync.aligned;" ::: "memory")
#define TCG_FENCE_AFTER() asm volatile("tcgen05.fence::after_thread_sync;" ::: "memory")

#define TCG_LD_X32(r, ta) \
    asm volatile("tcgen05.ld.sync.aligned.32x32b.x32.b32 " \
        "{%0,%1,%2,%3,%4,%5,%6,%7,%8,%9,%10,%11,%12,%13,%14,%15," \
        "%16,%17,%18,%19,%20,%21,%22,%23,%24,%25,%26,%27,%28,%29,%30,%31}, [%32];" \
        : "=r"((r)[0]), "=r"((r)[1]), "=r"((r)[2]), "=r"((r)[3]), \
          "=r"((r)[4]), "=r"((r)[5]), "=r"((r)[6]), "=r"((r)[7]), \
          "=r"((r)[8]), "=r"((r)[9]), "=r"((r)[10]), "=r"((r)[11]), \
          "=r"((r)[12]), "=r"((r)[13]), "=r"((r)[14]), "=r"((r)[15]), \
          "=r"((r)[16]), "=r"((r)[17]), "=r"((r)[18]), "=r"((r)[19]), \
          "=r"((r)[20]), "=r"((r)[21]), "=r"((r)[22]), "=r"((r)[23]), \
          "=r"((r)[24]), "=r"((r)[25]), "=r"((r)[26]), "=r"((r)[27]), \
          "=r"((r)[28]), "=r"((r)[29]), "=r"((r)[30]), "=r"((r)[31]) \
        : "r"(ta))
#endif  // HAS_TCGEN05

// ---------------------------------------------------------------------------
// Pass 1: X (B=64, C=128, H=32, W=32) -> XtH (H, W, B, C) fp16.
// One block per (b, y): smem plane (c=128, x=32).
// ---------------------------------------------------------------------------
__global__ void __launch_bounds__(256) transpose_kernel(const float* __restrict__ X) {
    __shared__ float sm[128][33];
    const int bx = blockIdx.x;
    const int b  = bx >> 5;    // 0..63
    const int yy = bx & 31;    // 0..31
    const int t  = threadIdx.x;

    #pragma unroll
    for (int p = 0; p < 16; p++) {
        const int c = p * 8 + (t >> 5);
        const int x = t & 31;
        sm[c][x] = X[(((b * 128 + c) * 32 + yy) << 5) + x];
    }
    __syncthreads();
    #pragma unroll
    for (int q = 0; q < 16; q++) {
        const int x = q * 2 + (t >> 7);
        const int c = t & 127;
        g_XtH[((size_t)(((yy << 5) + x) << 6) + b) * 128 + c] = __float2half_rn(sm[c][x]);
    }
}

// ---------------------------------------------------------------------------
// Pass 2: per-location GEMM (role-swapped, tap-major K64 chunks, fp16, 2-stage)
// smem (bytes): W(A) stages [0,16K); Act(B) stages [16K,32K);
//   mbar 32768 (2 x u64); tmem ptr 32784; cs4 [32800,33824); cs [33824,34080)
// ---------------------------------------------------------------------------
__global__ void __launch_bounds__(256, 4) varconv_kernel(
    const float* __restrict__ W, const float* __restrict__ bias)
{
    const int s = blockIdx.x;
    const int y = s >> 5, x0 = s & 31;
    const int tid = threadIdx.x;
    const float bs = bias[s];

#if HAS_TCGEN05
    __shared__ __align__(1024) uint32_t sm[8520];
    const uint32_t smb = smem_u32(sm);
    char* smc = (char*)sm;

    const int wid = tid >> 5, lid = tid & 31;
    const int bq = tid & 63;        // co row (W / A-operand)
    const int kg = tid >> 6;        // k-subgroup 0..3 (16 k each)

    if (wid == 0) { TCG_ALLOC(smb + 32784, 64); TCG_RELINQ(); }
    if (tid == 0) { MBARRIER_INIT(smb + 32768, 1); MBARRIER_INIT(smb + 32768 + 8, 1); }
    __syncthreads();
    uint32_t tmem;
    asm("ld.shared.b32 %0, [%1];" : "=r"(tmem) : "r"(smb + 32784));

    const float* Wp = W + (size_t)s * 73728 + bq;   // + co
    float csum = 0.0f;
    uint32_t wv[8];                 // 16 k as 8 x half2
    uint4 act0, act1;

    // Act fill: 8 lanes per b-row (16B granules of a 128B fp16 row, nL=1).
    const int r0 = tid >> 3, gj = tid & 7;

    // chunk ci = tap*2 + h; covers original k = ((h*64 + j)*9 + tap), j=0..63.
    auto loadAB = [&](int ci) {
        const int tap = ci >> 1;
        const int h   = ci & 1;
        const int yy  = y  + tap / 3 - 1;
        const int xx  = x0 + tap % 3 - 1;
        const int kb  = h * 64 + kg * 16;       // c-base for W rows
        const float* wq = Wp + (size_t)(kb * 9 + tap) * 64;
        #pragma unroll
        for (int u = 0; u < 8; u++) {
            const float w0 = __ldg(wq + (2 * u) * 576);
            const float w1 = __ldg(wq + (2 * u + 1) * 576);
            csum += w0 + w1;
            wv[u] = pack_f16x2(w0, w1);
        }
        if (((unsigned)yy < 32u) && ((unsigned)xx < 32u)) {
            const __half* base = g_XtH + (size_t)((((yy << 5) + xx) << 6)) * 128 + h * 64 + gj * 8;
            act0 = *(const uint4*)(base + (size_t)r0 * 128);
            act1 = *(const uint4*)(base + (size_t)(r0 + 32) * 128);
        } else {
            act0 = make_uint4(0, 0, 0, 0);
            act1 = make_uint4(0, 0, 0, 0);
        }
    };

    loadAB(0);
    int ph0 = 0, ph1 = 0;
    const uint32_t woff = (uint32_t)bq * 128 + (uint32_t)kg * 32;
    const uint32_t wsw0 = SWZ(woff), wsw1 = SWZ(woff + 16);
    const uint32_t asw0 = SWZ((uint32_t)r0 * 128 + (uint32_t)gj * 16);
    const uint32_t asw1 = SWZ((uint32_t)(r0 + 32) * 128 + (uint32_t)gj * 16);

#define CHUNK(I, ST, PH) { \
    if ((I) >= 2) { MBAR_WAIT(smb + 32768 + (ST) * 8, PH); PH ^= 1; } \
    *(uint4*)(smc + (ST) * 8192 + wsw0)         = make_uint4(wv[0], wv[1], wv[2], wv[3]); \
    *(uint4*)(smc + (ST) * 8192 + wsw1)         = make_uint4(wv[4], wv[5], wv[6], wv[7]); \
    *(uint4*)(smc + 16384 + (ST) * 8192 + asw0) = act0; \
    *(uint4*)(smc + 16384 + (ST) * 8192 + asw1) = act1; \
    if ((I) + 1 < 18) loadAB((I) + 1); \
    asm volatile("fence.proxy.async.shared::cta;" ::: "memory"); \
    __syncthreads(); \
    if (wid == 0 && elect_one()) { \
        uint64_t ad = make_desc(smb + (ST) * 8192); \
        uint64_t bd = make_desc(smb + 16384 + (ST) * 8192); \
        mma_f16(tmem, ad,     bd,     (I) > 0 ? 1u : 0u); \
        mma_f16(tmem, ad + 2, bd + 2, 1u); \
        mma_f16(tmem, ad + 4, bd + 4, 1u); \
        mma_f16(tmem, ad + 6, bd + 6, 1u); \
        TCG_COMMIT(smb + 32768 + (ST) * 8); \
    } }

    for (int i = 0; i < 18; i += 2) {
        CHUNK(i, 0, ph0);
        CHUNK(i + 1, 1, ph1);
    }
#undef CHUNK

    // colsum reduction: cs[co] = sum over 4 kg partials (raw f32 weights)
    ((float*)(smc + 32800))[kg * 64 + bq] = csum;
    __syncthreads();
    if (tid < 64) {
        const float* c4 = (const float*)(smc + 32800);
        ((float*)(smc + 33824))[tid] = c4[tid] + c4[64 + tid] + c4[128 + tid] + c4[192 + tid];
    }
    __syncthreads();

    MBAR_WAIT(smb + 32768, ph0);
    MBAR_WAIT(smb + 32768 + 8, ph1);
    TCG_FENCE_AFTER();

    // D[co][b]: warps 0,1 read rows co=0..63, add bias*colsum[co], write
    // scratch[s][co][b] coalesced.
    if (wid < 2) {
        const int co = wid * 32 + lid;
        const float corr = bs * ((const float*)(smc + 33824))[co];
        float* dst = g_scratch + ((size_t)s * 64 + co) * 64;
        uint32_t dr[32];
        TCG_LD_X32(dr, tmem);
        TCG_WAIT_LD();
        #pragma unroll
        for (int c = 0; c < 32; c++)
            dr[c] = __float_as_uint(__uint_as_float(dr[c]) + corr);
        #pragma unroll
        for (int j = 0; j < 8; j++)
            ((uint4*)dst)[j] = make_uint4(dr[4 * j], dr[4 * j + 1], dr[4 * j + 2], dr[4 * j + 3]);
        TCG_LD_X32(dr, tmem + 32);
        TCG_WAIT_LD();
        #pragma unroll
        for (int c = 0; c < 32; c++)
            dr[c] = __float_as_uint(__uint_as_float(dr[c]) + corr);
        #pragma unroll
        for (int j = 0; j < 8; j++)
            ((uint4*)(dst + 32))[j] = make_uint4(dr[4 * j], dr[4 * j + 1], dr[4 * j + 2], dr[4 * j + 3]);
    }
    __syncthreads();
    if (wid == 0) TCG_DEALLOC(tmem, 64);

#else  // ------- SIMT fallback (plain compute_103 pass; not selected on GB300)
    __shared__ float As[32][68];
    __shared__ float Bs[32][64];
    const int tx = tid & 15;
    const int ty = tid >> 4;
    const float* Wp = W + (size_t)s * 73728;

    float acc[4][4];
    #pragma unroll
    for (int i = 0; i < 4; i++)
        #pragma unroll
        for (int j = 0; j < 4; j++) acc[i][j] = 0.0f;

    for (int k0 = 0; k0 < 1152; k0 += 32) {
        {
            const float4* src = (const float4*)(Wp + k0 * 64);
            float4* dstB = (float4*)(&Bs[0][0]);
            dstB[tid]       = src[tid];
            dstB[tid + 256] = src[tid + 256];
        }
        #pragma unroll
        for (int i = 0; i < 2; i++) {
            const int kk = i * 16 + (tid >> 4);
            const int k  = k0 + kk;
            const int c   = k / 9;
            const int tap = k - c * 9;
            const int r   = tap / 3;
            const int cc  = tap - r * 3;
            const int yy = y + r - 1;
            const int xx = x0 + cc - 1;
            const int b4 = (tid & 15) << 2;
            float4 v = make_float4(0.f, 0.f, 0.f, 0.f);
            if (((unsigned)yy < 32u) && ((unsigned)xx < 32u)) {
                v.x = __half2float(g_XtH[((size_t)(((yy << 5) + xx) << 6) + b4 + 0) * 128 + c]);
                v.y = __half2float(g_XtH[((size_t)(((yy << 5) + xx) << 6) + b4 + 1) * 128 + c]);
                v.z = __half2float(g_XtH[((size_t)(((yy << 5) + xx) << 6) + b4 + 2) * 128 + c]);
                v.w = __half2float(g_XtH[((size_t)(((yy << 5) + xx) << 6) + b4 + 3) * 128 + c]);
            }
            v.x += bs; v.y += bs; v.z += bs; v.w += bs;
            *(float4*)&As[kk][b4] = v;
        }
        __syncthreads();
        #pragma unroll
        for (int kk = 0; kk < 32; kk++) {
            const float4 a = *(const float4*)&As[kk][ty << 2];
            const float4 b = *(const float4*)&Bs[kk][tx << 2];
            acc[0][0] += a.x * b.x; acc[0][1] += a.x * b.y; acc[0][2] += a.x * b.z; acc[0][3] += a.x * b.w;
            acc[1][0] += a.y * b.x; acc[1][1] += a.y * b.y; acc[1][2] += a.y * b.z; acc[1][3] += a.y * b.w;
            acc[2][0] += a.z * b.x; acc[2][1] += a.z * b.y; acc[2][2] += a.z * b.z; acc[2][3] += a.z * b.w;
            acc[3][0] += a.w * b.x; acc[3][1] += a.w * b.y; acc[3][2] += a.w * b.z; acc[3][3] += a.w * b.w;
        }
        __syncthreads();
    }
    #pragma unroll
    for (int i = 0; i < 4; i++) {
        const int b = (ty << 2) + i;
        #pragma unroll
        for (int j = 0; j < 4; j++) {
            const int co = (tx << 2) + j;
            g_scratch[((size_t)s * 64 + co) * 64 + b] = acc[i][j];
        }
    }
#endif
}

// ---------------------------------------------------------------------------
// Pass 3: scratch (s, co, b) -> out (b*64+co, s)
// ---------------------------------------------------------------------------
__global__ void __launch_bounds__(256) out_transpose(float* __restrict__ out) {
    __shared__ float tile[64][65];   // [s][b]
    const int co = blockIdx.x;
    const int s0 = blockIdx.y * 64;
    const int t  = threadIdx.x;

    #pragma unroll
    for (int r = 0; r < 4; r++) {
        const int gi = r * 256 + t;
        const int si = gi >> 4;
        const int gjj = gi & 15;
        const float4 v = *(const float4*)(g_scratch + (size_t)(s0 + si) * 4096 + co * 64 + gjj * 4);
        tile[si][gjj * 4 + 0] = v.x;
        tile[si][gjj * 4 + 1] = v.y;
        tile[si][gjj * 4 + 2] = v.z;
        tile[si][gjj * 4 + 3] = v.w;
    }
    __syncthreads();
    #pragma unroll
    for (int r = 0; r < 4; r++) {
        const int gi = r * 256 + t;
        const int b  = gi >> 4;
        const int sj = gi & 15;
        float4 v;
        v.x = tile[sj * 4 + 0][b];
        v.y = tile[sj * 4 + 1][b];
        v.z = tile[sj * 4 + 2][b];
        v.w = tile[sj * 4 + 3][b];
        *(float4*)(out + (size_t)(b * 64 + co) * 1024 + s0 + sj * 4) = v;
    }
}

extern "C" void kernel_launch(void* const* d_in, const int* in_sizes, int n_in,
                              void* d_out, int out_size) {
    const float* X    = (const float*)d_in[0];
    const float* W    = (const float*)d_in[1];
    const float* bias = (const float*)d_in[2];
    float* out = (float*)d_out;

    transpose_kernel<<<64 * 32, 256>>>(X);
    varconv_kernel<<<1024, 256>>>(W, bias);
    out_transpose<<<dim3(64, 16), 256>>>(out);
}

// round 16
// speedup vs baseline: 1.6682x; 1.0379x over previous
#include <cuda_runtime.h>
#include <cuda_fp16.h>
#include <cstdint>

// VarConvND via tcgen05 FP16 per-location GEMM (sm_103a), SIMT fallback body
// for the plain compute_103 PTX pass (never selected at runtime on GB300).
//
//   out[b, co, s] = sum_k (unfold(X)[b, k, s] + bias[s]) * weight[s, k, co]
// Decomposed: out = unfold(X)^T W + bias[s] * colsum_k(W[s,:,co]).
//
// ROLE SWAP: A-operand = W[co][k] (M=co pad 128), B-operand = act[b][k] (N=64).
// K permuted tap-major; chunk = (tap, c-half): K64 per chunk, 18 chunks.
// Round 14: W fill uses LDG.64 (2 co x 8 k per thread, warp = one k-octet);
// pass-1 stores are packed half2 (full-sector STG.32).
//
// Pass 1: X (B,C,H,W) -> XtH (H,W,B,C) fp16 (rn).
// Pass 2: one block per s, 2-stage pipeline. D[co][b] -> scratch[s][co][b].
// Pass 3: scratch (s, co, b) -> out (b*64+co, s).

#if defined(__CUDA_ARCH_FEAT_SM103_ALL) || defined(__CUDA_ARCH_FEAT_SM100_ALL)
#define HAS_TCGEN05 1
#else
#define HAS_TCGEN05 0
#endif

__device__ __half g_XtH[32 * 32 * 64 * 128];    // (y, x, b, c) 16.8 MB
__device__ float g_scratch[1024 * 64 * 64];     // (s, co, b)   16.8 MB

// ---------------------------------------------------------------------------
// helpers
// ---------------------------------------------------------------------------
__device__ __forceinline__ uint32_t smem_u32(const void* p) {
    uint32_t a;
    asm("{ .reg .u64 t; cvta.to.shared.u64 t, %1; cvt.u32.u64 %0, t; }" : "=r"(a) : "l"(p));
    return a;
}
__device__ __forceinline__ uint32_t pack_f16x2(float lo, float hi) {
    uint32_t r;
    asm("cvt.rn.f16x2.f32 %0, %1, %2;" : "=r"(r) : "f"(hi), "f"(lo));
    return r;
}
#define SWZ(o) ((o) ^ (((o) >> 3) & 0x70))

#if HAS_TCGEN05
__device__ __forceinline__ uint32_t elect_one() {
    uint32_t p;
    asm volatile("{ .reg .pred p; elect.sync _|p, 0xFFFFFFFF; selp.b32 %0,1,0,p; }" : "=r"(p));
    return p;
}

// K-major SW128: LBO=1, SBO=64 (proven rounds 4-13; 128B rows)
static constexpr uint64_t DESC_BASE =
    (uint64_t(2) << 61) | (uint64_t(1) << 46) | (uint64_t(64) << 32) | (uint64_t(1) << 16);
__device__ __forceinline__ uint64_t make_desc(uint32_t addr) {
    return DESC_BASE | ((uint64_t)(addr >> 4) & 0x3FFF);
}

// idesc kind::f16 (fp16 x fp16 -> f32): dtype=F32(1)<<4, atype=FP16(0)<<7,
// btype=FP16(0)<<10, N=64 -> 8<<17, M=128 -> 8<<24   (proven round 13)
#define IDESC_F16 0x8100010u

__device__ __forceinline__ void mma_f16(uint32_t d, uint64_t ad, uint64_t bd, uint32_t en) {
    asm volatile(
        "{\n\t.reg .pred p;\n\tsetp.ne.u32 p, %4, 0;\n\t"
        "tcgen05.mma.cta_group::1.kind::f16 [%0], %1, %2, %3, {%5,%5,%5,%5}, p;\n\t}"
        :: "r"(d), "l"(ad), "l"(bd), "r"(IDESC_F16), "r"(en), "r"(0u) : "memory");
}

#define MBARRIER_INIT(a, c) \
    asm volatile("mbarrier.init.shared.b64 [%0], %1;" :: "r"(a), "r"(c) : "memory")

#define MBAR_WAIT(addr, ph) do { \
    uint32_t _a = (addr), _p = (ph) & 1, _d; \
    asm volatile("{\n\t.reg .pred p;\n\tmbarrier.try_wait.parity.acquire.cta.shared::cta.b64 p, [%1], %2;\n\tselp.b32 %0,1,0,p;\n\t}" \
        : "=r"(_d) : "r"(_a), "r"(_p) : "memory"); \
    while (!_d) { \
        asm volatile("{\n\t.reg .pred p;\n\tmbarrier.try_wait.parity.acquire.cta.shared::cta.b64 p, [%1], %2, 0x989680;\n\tselp.b32 %0,1,0,p;\n\t}" \
            : "=r"(_d) : "r"(_a), "r"(_p) : "memory"); \
    } \
} while (0)

#define TCG_COMMIT(mb) \
    asm volatile("tcgen05.commit.cta_group::1.mbarrier::arrive::one.shared::cluster.b64 [%0];" :: "r"(mb) : "memory")
#define TCG_ALLOC(sa, n) \
    asm volatile("tcgen05.alloc.cta_group::1.sync.aligned.shared::cta.b32 [%0], %1;" :: "r"(sa), "r"(n) : "memory")
#define TCG_DEALLOC(t, n) \
    asm volatile("tcgen05.dealloc.cta_group::1.sync.aligned.b32 %0, %1;" :: "r"(t), "r"(n))
#define TCG_RELINQ() \
    asm volatile("tcgen05.relinquish_alloc_permit.cta_group::1.sync.aligned;")
#define TCG_WAIT_LD() asm volatile("tcgen05.wait::ld.sync.aligned;" ::: "memory")
#define TCG_FENCE_AFTER() asm volatile("tcgen05.fence::after_thread_sync;" ::: "memory")

#define TCG_LD_X32(r, ta) \
    asm volatile("tcgen05.ld.sync.aligned.32x32b.x32.b32 " \
        "{%0,%1,%2,%3,%4,%5,%6,%7,%8,%9,%10,%11,%12,%13,%14,%15," \
        "%16,%17,%18,%19,%20,%21,%22,%23,%24,%25,%26,%27,%28,%29,%30,%31}, [%32];" \
        : "=r"((r)[0]), "=r"((r)[1]), "=r"((r)[2]), "=r"((r)[3]), \
          "=r"((r)[4]), "=r"((r)[5]), "=r"((r)[6]), "=r"((r)[7]), \
          "=r"((r)[8]), "=r"((r)[9]), "=r"((r)[10]), "=r"((r)[11]), \
          "=r"((r)[12]), "=r"((r)[13]), "=r"((r)[14]), "=r"((r)[15]), \
          "=r"((r)[16]), "=r"((r)[17]), "=r"((r)[18]), "=r"((r)[19]), \
          "=r"((r)[20]), "=r"((r)[21]), "=r"((r)[22]), "=r"((r)[23]), \
          "=r"((r)[24]), "=r"((r)[25]), "=r"((r)[26]), "=r"((r)[27]), \
          "=r"((r)[28]), "=r"((r)[29]), "=r"((r)[30]), "=r"((r)[31]) \
        : "r"(ta))
#endif  // HAS_TCGEN05

// ---------------------------------------------------------------------------
// Pass 1: X (B=64, C=128, H=32, W=32) -> XtH (H, W, B, C) fp16.
// One block per (b, y): smem plane (c=128, x=32). Packed half2 stores.
// ---------------------------------------------------------------------------
__global__ void __launch_bounds__(256) transpose_kernel(const float* __restrict__ X) {
    __shared__ float sm[128][33];
    const int bx = blockIdx.x;
    const int b  = bx >> 5;    // 0..63
    const int yy = bx & 31;    // 0..31
    const int t  = threadIdx.x;

    #pragma unroll
    for (int p = 0; p < 16; p++) {
        const int c = p * 8 + (t >> 5);
        const int x = t & 31;
        sm[c][x] = X[(((b * 128 + c) * 32 + yy) << 5) + x];
    }
    __syncthreads();
    // 8 iters: thread handles c-pair c2 = t&63, x = q*4 + (t>>6)
    const int c2 = t & 63;
    #pragma unroll
    for (int q = 0; q < 8; q++) {
        const int x = q * 4 + (t >> 6);
        const uint32_t h2 = pack_f16x2(sm[c2 * 2][x], sm[c2 * 2 + 1][x]);
        *(uint32_t*)&g_XtH[((size_t)((((yy << 5) + x) << 6) + b)) * 128 + c2 * 2] = h2;
    }
}

// ---------------------------------------------------------------------------
// Pass 2: per-location GEMM (role-swapped, tap-major K64 chunks, fp16, 2-stage)
// smem (bytes): W(A) stages [0,16K); Act(B) stages [16K,32K);
//   mbar 32768 (2 x u64); tmem ptr 32784; cs8 [32800,34848); cs [34848,35104)
// ---------------------------------------------------------------------------
__global__ void __launch_bounds__(256, 4) varconv_kernel(
    const float* __restrict__ W, const float* __restrict__ bias)
{
    const int s = blockIdx.x;
    const int y = s >> 5, x0 = s & 31;
    const int tid = threadIdx.x;
    const float bs = bias[s];

#if HAS_TCGEN05
    __shared__ __align__(1024) uint32_t sm[8800];
    const uint32_t smb = smem_u32(sm);
    char* smc = (char*)sm;

    const int wid = tid >> 5, lid = tid & 31;
    const int cog = lid * 2;        // co base (even), 2 co per thread
    const int wkq = wid;            // warp id = k-octet 0..7

    if (wid == 0) { TCG_ALLOC(smb + 32784, 64); TCG_RELINQ(); }
    if (tid == 0) { MBARRIER_INIT(smb + 32768, 1); MBARRIER_INIT(smb + 32768 + 8, 1); }
    __syncthreads();
    uint32_t tmem;
    asm("ld.shared.b32 %0, [%1];" : "=r"(tmem) : "r"(smb + 32784));

    const float* Wbase = W + (size_t)s * 73728 + cog;
    float csum0 = 0.0f, csum1 = 0.0f;
    uint32_t wv[8];                 // rows cog (wv[0..3]) and cog+1 (wv[4..7])
    uint4 act0, act1;

    // Act fill: 8 lanes per b-row (16B granules of a 128B fp16 row, nL=1).
    const int r0 = tid >> 3, gj = tid & 7;

    // chunk ci = tap*2 + h; covers original k = ((h*64 + j)*9 + tap), j=0..63.
    auto loadAB = [&](int ci) {
        const int tap = ci >> 1;
        const int h   = ci & 1;
        const int yy  = y  + tap / 3 - 1;
        const int xx  = x0 + tap % 3 - 1;
        const int kb  = h * 64 + wkq * 8;       // c-base for this warp's octet
        const float* wq = Wbase + (size_t)(kb * 9 + tap) * 64;
        float2 wf[8];
        #pragma unroll
        for (int u = 0; u < 8; u++)
            wf[u] = __ldg((const float2*)(wq + (size_t)u * 576));
        #pragma unroll
        for (int u = 0; u < 8; u++) { csum0 += wf[u].x; csum1 += wf[u].y; }
        wv[0] = pack_f16x2(wf[0].x, wf[1].x);
        wv[1] = pack_f16x2(wf[2].x, wf[3].x);
        wv[2] = pack_f16x2(wf[4].x, wf[5].x);
        wv[3] = pack_f16x2(wf[6].x, wf[7].x);
        wv[4] = pack_f16x2(wf[0].y, wf[1].y);
        wv[5] = pack_f16x2(wf[2].y, wf[3].y);
        wv[6] = pack_f16x2(wf[4].y, wf[5].y);
        wv[7] = pack_f16x2(wf[6].y, wf[7].y);
        if (((unsigned)yy < 32u) && ((unsigned)xx < 32u)) {
            const __half* base = g_XtH + (size_t)((((yy << 5) + xx) << 6)) * 128 + h * 64 + gj * 8;
            act0 = *(const uint4*)(base + (size_t)r0 * 128);
            act1 = *(const uint4*)(base + (size_t)(r0 + 32) * 128);
        } else {
            act0 = make_uint4(0, 0, 0, 0);
            act1 = make_uint4(0, 0, 0, 0);
        }
    };

    loadAB(0);
    int ph0 = 0, ph1 = 0;
    const uint32_t wswA = SWZ((uint32_t)cog * 128 + (uint32_t)wkq * 16);
    const uint32_t wswB = SWZ((uint32_t)(cog + 1) * 128 + (uint32_t)wkq * 16);
    const uint32_t asw0 = SWZ((uint32_t)r0 * 128 + (uint32_t)gj * 16);
    const uint32_t asw1 = SWZ((uint32_t)(r0 + 32) * 128 + (uint32_t)gj * 16);

#define CHUNK(I, ST, PH) { \
    if ((I) >= 2) { MBAR_WAIT(smb + 32768 + (ST) * 8, PH); PH ^= 1; } \
    *(uint4*)(smc + (ST) * 8192 + wswA)         = make_uint4(wv[0], wv[1], wv[2], wv[3]); \
    *(uint4*)(smc + (ST) * 8192 + wswB)         = make_uint4(wv[4], wv[5], wv[6], wv[7]); \
    *(uint4*)(smc + 16384 + (ST) * 8192 + asw0) = act0; \
    *(uint4*)(smc + 16384 + (ST) * 8192 + asw1) = act1; \
    if ((I) + 1 < 18) loadAB((I) + 1); \
    asm volatile("fence.proxy.async.shared::cta;" ::: "memory"); \
    __syncthreads(); \
    if (wid == 0 && elect_one()) { \
        uint64_t ad = make_desc(smb + (ST) * 8192); \
        uint64_t bd = make_desc(smb + 16384 + (ST) * 8192); \
        mma_f16(tmem, ad,     bd,     (I) > 0 ? 1u : 0u); \
        mma_f16(tmem, ad + 2, bd + 2, 1u); \
        mma_f16(tmem, ad + 4, bd + 4, 1u); \
        mma_f16(tmem, ad + 6, bd + 6, 1u); \
        TCG_COMMIT(smb + 32768 + (ST) * 8); \
    } }

    for (int i = 0; i < 18; i += 2) {
        CHUNK(i, 0, ph0);
        CHUNK(i + 1, 1, ph1);
    }
#undef CHUNK

    // colsum: 8 k-octet partials per co (raw f32 weights)
    ((float2*)(smc + 32800))[(wkq * 64 + cog) >> 1] = make_float2(csum0, csum1);
    __syncthreads();
    if (tid < 64) {
        const float* c8 = (const float*)(smc + 32800);
        float v = 0.0f;
        #pragma unroll
        for (int j = 0; j < 8; j++) v += c8[j * 64 + tid];
        ((float*)(smc + 34848))[tid] = v;
    }
    __syncthreads();

    MBAR_WAIT(smb + 32768, ph0);
    MBAR_WAIT(smb + 32768 + 8, ph1);
    TCG_FENCE_AFTER();

    // D[co][b]: warps 0,1 read rows co=0..63, add bias*colsum[co], write
    // scratch[s][co][b] coalesced.
    if (wid < 2) {
        const int co = wid * 32 + lid;
        const float corr = bs * ((const float*)(smc + 34848))[co];
        float* dst = g_scratch + ((size_t)s * 64 + co) * 64;
        uint32_t dr[32];
        TCG_LD_X32(dr, tmem);
        TCG_WAIT_LD();
        #pragma unroll
        for (int c = 0; c < 32; c++)
            dr[c] = __float_as_uint(__uint_as_float(dr[c]) + corr);
        #pragma unroll
        for (int j = 0; j < 8; j++)
            ((uint4*)dst)[j] = make_uint4(dr[4 * j], dr[4 * j + 1], dr[4 * j + 2], dr[4 * j + 3]);
        TCG_LD_X32(dr, tmem + 32);
        TCG_WAIT_LD();
        #pragma unroll
        for (int c = 0; c < 32; c++)
            dr[c] = __float_as_uint(__uint_as_float(dr[c]) + corr);
        #pragma unroll
        for (int j = 0; j < 8; j++)
            ((uint4*)(dst + 32))[j] = make_uint4(dr[4 * j], dr[4 * j + 1], dr[4 * j + 2], dr[4 * j + 3]);
    }
    __syncthreads();
    if (wid == 0) TCG_DEALLOC(tmem, 64);

#else  // ------- SIMT fallback (plain compute_103 pass; not selected on GB300)
    __shared__ float As[32][68];
    __shared__ float Bs[32][64];
    const int tx = tid & 15;
    const int ty = tid >> 4;
    const float* Wp = W + (size_t)s * 73728;

    float acc[4][4];
    #pragma unroll
    for (int i = 0; i < 4; i++)
        #pragma unroll
        for (int j = 0; j < 4; j++) acc[i][j] = 0.0f;

    for (int k0 = 0; k0 < 1152; k0 += 32) {
        {
            const float4* src = (const float4*)(Wp + k0 * 64);
            float4* dstB = (float4*)(&Bs[0][0]);
            dstB[tid]       = src[tid];
            dstB[tid + 256] = src[tid + 256];
        }
        #pragma unroll
        for (int i = 0; i < 2; i++) {
            const int kk = i * 16 + (tid >> 4);
            const int k  = k0 + kk;
            const int c   = k / 9;
            const int tap = k - c * 9;
            const int r   = tap / 3;
            const int cc  = tap - r * 3;
            const int yy = y + r - 1;
            const int xx = x0 + cc - 1;
            const int b4 = (tid & 15) << 2;
            float4 v = make_float4(0.f, 0.f, 0.f, 0.f);
            if (((unsigned)yy < 32u) && ((unsigned)xx < 32u)) {
                v.x = __half2float(g_XtH[((size_t)(((yy << 5) + xx) << 6) + b4 + 0) * 128 + c]);
                v.y = __half2float(g_XtH[((size_t)(((yy << 5) + xx) << 6) + b4 + 1) * 128 + c]);
                v.z = __half2float(g_XtH[((size_t)(((yy << 5) + xx) << 6) + b4 + 2) * 128 + c]);
                v.w = __half2float(g_XtH[((size_t)(((yy << 5) + xx) << 6) + b4 + 3) * 128 + c]);
            }
            v.x += bs; v.y += bs; v.z += bs; v.w += bs;
            *(float4*)&As[kk][b4] = v;
        }
        __syncthreads();
        #pragma unroll
        for (int kk = 0; kk < 32; kk++) {
            const float4 a = *(const float4*)&As[kk][ty << 2];
            const float4 b = *(const float4*)&Bs[kk][tx << 2];
            acc[0][0] += a.x * b.x; acc[0][1] += a.x * b.y; acc[0][2] += a.x * b.z; acc[0][3] += a.x * b.w;
            acc[1][0] += a.y * b.x; acc[1][1] += a.y * b.y; acc[1][2] += a.y * b.z; acc[1][3] += a.y * b.w;
            acc[2][0] += a.z * b.x; acc[2][1] += a.z * b.y; acc[2][2] += a.z * b.z; acc[2][3] += a.z * b.w;
            acc[3][0] += a.w * b.x; acc[3][1] += a.w * b.y; acc[3][2] += a.w * b.z; acc[3][3] += a.w * b.w;
        }
        __syncthreads();
    }
    #pragma unroll
    for (int i = 0; i < 4; i++) {
        const int b = (ty << 2) + i;
        #pragma unroll
        for (int j = 0; j < 4; j++) {
            const int co = (tx << 2) + j;
            g_scratch[((size_t)s * 64 + co) * 64 + b] = acc[i][j];
        }
    }
#endif
}

// ---------------------------------------------------------------------------
// Pass 3: scratch (s, co, b) -> out (b*64+co, s)
// ---------------------------------------------------------------------------
__global__ void __launch_bounds__(256) out_transpose(float* __restrict__ out) {
    __shared__ float tile[64][65];   // [s][b]
    const int co = blockIdx.x;
    const int s0 = blockIdx.y * 64;
    const int t  = threadIdx.x;

    #pragma unroll
    for (int r = 0; r < 4; r++) {
        const int gi = r * 256 + t;
        const int si = gi >> 4;
        const int gjj = gi & 15;
        const float4 v = *(const float4*)(g_scratch + (size_t)(s0 + si) * 4096 + co * 64 + gjj * 4);
        tile[si][gjj * 4 + 0] = v.x;
        tile[si][gjj * 4 + 1] = v.y;
        tile[si][gjj * 4 + 2] = v.z;
        tile[si][gjj * 4 + 3] = v.w;
    }
    __syncthreads();
    #pragma unroll
    for (int r = 0; r < 4; r++) {
        const int gi = r * 256 + t;
        const int b  = gi >> 4;
        const int sj = gi & 15;
        float4 v;
        v.x = tile[sj * 4 + 0][b];
        v.y = tile[sj * 4 + 1][b];
        v.z = tile[sj * 4 + 2][b];
        v.w = tile[sj * 4 + 3][b];
        *(float4*)(out + (size_t)(b * 64 + co) * 1024 + s0 + sj * 4) = v;
    }
}

extern "C" void kernel_launch(void* const* d_in, const int* in_sizes, int n_in,
                              void* d_out, int out_size) {
    const float* X    = (const float*)d_in[0];
    const float* W    = (const float*)d_in[1];
    const float* bias = (const float*)d_in[2];
    float* out = (float*)d_out;

    transpose_kernel<<<64 * 32, 256>>>(X);
    varconv_kernel<<<1024, 256>>>(W, bias);
    out_transpose<<<dim3(64, 16), 256>>>(out);
}